// round 14
// baseline (speedup 1.0000x reference)
#include <cuda_runtime.h>
#include <cuda_bf16.h>
#include <cuda_fp16.h>

// Geometry
#define H 512
#define W 512
#define N_ANGLES 512
#define N_DET 736
#define N_SAMP 736

// Full-range padding: all sample coords in-bounds; outside-support reads 0.
#define PAD 272
#define PW 1056            // divisible by 4
#define PH 1056
#define TW (PW / 4)        // 264 tiles per row

// fp16 quad image in 4x4-pixel tiled layout (one 128B line == 4x4 px block).
//   .x = half2( I[y][x],   I[y][x+1]   )
//   .y = half2( I[y+1][x], I[y+1][x+1] )
__device__ uint2 g_quadh[PH * PW];

__device__ __forceinline__ int tiled_idx(int y, int x) {
    return (((y >> 2) * TW + (x >> 2)) << 4) + ((y & 3) << 2) + (x & 3);
}

// ---------------------------------------------------------------------------
__global__ void build_quadh_kernel(const float* __restrict__ xin,
                                   const float* __restrict__ rin) {
    int idx = blockIdx.x * blockDim.x + threadIdx.x;
    if (idx >= PH * PW) return;
    int yq = idx / PW;
    int xq = idx - yq * PW;
    int y = yq - PAD;
    int x = xq - PAD;

    float v00 = 0.f, v01 = 0.f, v10 = 0.f, v11 = 0.f;
    if (y >= 0 && y < H) {
        if (x >= 0 && x < W)         v00 = xin[y * W + x]     + rin[y * W + x];
        if (x + 1 >= 0 && x + 1 < W) v01 = xin[y * W + x + 1] + rin[y * W + x + 1];
    }
    if (y + 1 >= 0 && y + 1 < H) {
        int y1 = y + 1;
        if (x >= 0 && x < W)         v10 = xin[y1 * W + x]     + rin[y1 * W + x];
        if (x + 1 >= 0 && x + 1 < W) v11 = xin[y1 * W + x + 1] + rin[y1 * W + x + 1];
    }

    __half2 h0 = __floats2half2_rn(v00, v01);
    __half2 h1 = __floats2half2_rn(v10, v11);
    uint2 q;
    q.x = *reinterpret_cast<unsigned int*>(&h0);
    q.y = *reinterpret_cast<unsigned int*>(&h1);
    g_quadh[tiled_idx(yq, xq)] = q;
}

__global__ void copy_reco_kernel(const float4* __restrict__ src,
                                 float4* __restrict__ dst, int n4) {
    int i = blockIdx.x * blockDim.x + threadIdx.x;
    if (i < n4) dst[i] = src[i];
}

// ---------------------------------------------------------------------------
// grid = (23, 128): blockIdx.y = 4-angle group, blockIdx.x = 32-detector block.
// block = 256 = 8 warps; each warp: 4 angles x 4 detectors x 2 t-phases.
// lane = aq*8 + tq*4 + dq. Lane samples t-index n = 2*it + tq.
// Per-lane chord predication: outside [it0,it1) the gather is predicated off.
// ---------------------------------------------------------------------------
__global__ void __launch_bounds__(256, 6)
project_kernel(const float* __restrict__ angles, float* __restrict__ sino) {
    const int lane = threadIdx.x & 31;
    const int warp = threadIdx.x >> 5;
    const int aq = lane >> 3;          // 0..3
    const int tq = (lane >> 2) & 1;    // 0..1
    const int dq = lane & 3;           // 0..3

    const int angle = blockIdx.y * 4 + aq;
    const int d = blockIdx.x * 32 + warp * 4 + dq;

    const float theta = __ldg(&angles[angle]);
    float si, c;
    sincosf(theta, &si, &c);

    const float s = (float)d - 367.5f;
    const float CTR = 255.5f + (float)PAD;        // 527.5

    // px(n) = s*c - (n - 367.5)*si + CTR, n = 2*it + tq
    const float BX = s * c + (367.5f - (float)tq) * si + CTR;
    const float BY = s * si - (367.5f - (float)tq) * c + CTR;
    const float DX = -2.0f * si;
    const float DY = 2.0f * c;

    // ---- exact chord clipping (unpadded coords), per lane ----
    const float A = s * c + 255.5f;
    const float B = s * si + 255.5f;
    float tlo = -368.0f, thi = 368.0f;
    if (fabsf(si) > 1e-6f) {
        float u1 = (A - 512.0f) / si, u2 = (A + 1.0f) / si;
        tlo = fmaxf(tlo, fminf(u1, u2));
        thi = fminf(thi, fmaxf(u1, u2));
    } else if (A <= -1.0f || A >= 512.0f) {
        thi = tlo;
    }
    if (fabsf(c) > 1e-6f) {
        float u1 = (-1.0f - B) / c, u2 = (512.0f - B) / c;
        tlo = fmaxf(tlo, fminf(u1, u2));
        thi = fminf(thi, fmaxf(u1, u2));
    } else if (B <= -1.0f || B >= 512.0f) {
        thi = tlo;
    }
    // lane's it-range (n = 2*it + tq); slack safe (padding reads 0)
    int it0 = __float2int_rd((tlo + 367.5f - (float)tq) * 0.5f);
    int it1 = __float2int_ru((thi + 367.5f - (float)tq) * 0.5f) + 1;
    it0 = min(max(it0, 0), N_SAMP / 2);
    it1 = min(max(it1, it0), N_SAMP / 2);

    const int wit0 = __reduce_min_sync(0xFFFFFFFFu, it0);
    const int wit1 = __reduce_max_sync(0xFFFFFFFFu, it1);

    float px = BX + (float)wit0 * DX;
    float py = BY + (float)wit0 * DY;
    float acc = 0.0f;

#pragma unroll 4
    for (int it = wit0; it < wit1; ++it) {
        const int xi = __float2int_rd(px);       // coords always positive
        const int yi = __float2int_rd(py);
        const float fx = px - (float)xi;
        const float fy = py - (float)yi;
        const int idx = (((yi >> 2) * TW + (xi >> 2)) << 4)
                        + ((yi & 3) << 2) + (xi & 3);
        uint2 q = make_uint2(0u, 0u);
        if (it >= it0 && it < it1)               // predicated gather
            q = __ldg(&g_quadh[idx]);
        const __half2 h0 = *reinterpret_cast<const __half2*>(&q.x);
        const __half2 h1 = *reinterpret_cast<const __half2*>(&q.y);
        const float2 f0 = __half22float2(h0);    // (v00, v01)
        const float2 f1 = __half22float2(h1);    // (v10, v11)
        const float top = fmaf(fx, f0.y - f0.x, f0.x);
        const float bot = fmaf(fx, f1.y - f1.x, f1.x);
        acc = fmaf(fy, bot - top, acc + top);
        px += DX;
        py += DY;
    }

    // reduce over tq (lane bit 2)
    acc += __shfl_xor_sync(0xFFFFFFFFu, acc, 4);

    if (tq == 0) {
        sino[angle * N_DET + d] = acc;   // STEP = 1.0
    }
}

// ---------------------------------------------------------------------------
extern "C" void kernel_launch(void* const* d_in, const int* in_sizes, int n_in,
                              void* d_out, int out_size) {
    const float* xin    = (const float*)d_in[0];   // [1,512,512]
    const float* rin    = (const float*)d_in[1];   // [1,512,512]
    const float* angles = (const float*)d_in[2];   // [512]

    float* out = (float*)d_out;
    float* sino_out = out;                         // [1,512,736]
    float* reco_out = out + N_ANGLES * N_DET;      // [1,512,512]

    {
        int total = PH * PW;
        int threads = 256;
        int blocks = (total + threads - 1) / threads;
        build_quadh_kernel<<<blocks, threads>>>(xin, rin);
    }
    {
        int n4 = (H * W) / 4;
        int threads = 256;
        int blocks = (n4 + threads - 1) / threads;
        copy_reco_kernel<<<blocks, threads>>>((const float4*)rin, (float4*)reco_out, n4);
    }
    {
        dim3 grid(N_DET / 32, N_ANGLES / 4);       // (23, 128)
        project_kernel<<<grid, 256>>>(angles, sino_out);
    }
}

// round 17
// speedup vs baseline: 1.2132x; 1.2132x over previous
#include <cuda_runtime.h>
#include <cuda_bf16.h>
#include <cuda_fp16.h>

// Geometry
#define H 512
#define W 512
#define N_ANGLES 512
#define N_DET 736
#define N_SAMP 736

// Full-range padding: all sample coords in-bounds; outside-support reads 0.
#define PAD 272
#define PW 1056            // divisible by 4
#define PH 1056
#define TW (PW / 4)        // 264 tiles per row

// fp16 quad image in 4x4-pixel tiled layout (one 128B line == 4x4 px block).
//   .x = half2( I[y][x],   I[y][x+1]   )
//   .y = half2( I[y+1][x], I[y+1][x+1] )
__device__ uint2 g_quadh[PH * PW];

__device__ __forceinline__ int tiled_idx(int y, int x) {
    return (((y >> 2) * TW + (x >> 2)) << 4) + ((y & 3) << 2) + (x & 3);
}

#define QUAD_BLOCKS ((PH * PW + 255) / 256)    // 4356
#define COPY_BLOCKS 256                        // 256*256 float4 = 262144 floats

// ---------------------------------------------------------------------------
// Fused: blocks [0, QUAD_BLOCKS) build the quad image; the last COPY_BLOCKS
// blocks copy reco to the output tail (vectorized float4).
// ---------------------------------------------------------------------------
__global__ void build_and_copy_kernel(const float* __restrict__ xin,
                                      const float* __restrict__ rin,
                                      float4* __restrict__ reco_out4) {
    if (blockIdx.x >= QUAD_BLOCKS) {
        int i = (blockIdx.x - QUAD_BLOCKS) * blockDim.x + threadIdx.x;
        reco_out4[i] = reinterpret_cast<const float4*>(rin)[i];
        return;
    }
    int idx = blockIdx.x * blockDim.x + threadIdx.x;
    if (idx >= PH * PW) return;
    int yq = idx / PW;
    int xq = idx - yq * PW;
    int y = yq - PAD;
    int x = xq - PAD;

    float v00 = 0.f, v01 = 0.f, v10 = 0.f, v11 = 0.f;
    if (y >= 0 && y < H) {
        if (x >= 0 && x < W)         v00 = xin[y * W + x]     + rin[y * W + x];
        if (x + 1 >= 0 && x + 1 < W) v01 = xin[y * W + x + 1] + rin[y * W + x + 1];
    }
    if (y + 1 >= 0 && y + 1 < H) {
        int y1 = y + 1;
        if (x >= 0 && x < W)         v10 = xin[y1 * W + x]     + rin[y1 * W + x];
        if (x + 1 >= 0 && x + 1 < W) v11 = xin[y1 * W + x + 1] + rin[y1 * W + x + 1];
    }

    __half2 h0 = __floats2half2_rn(v00, v01);
    __half2 h1 = __floats2half2_rn(v10, v11);
    uint2 q;
    q.x = *reinterpret_cast<unsigned int*>(&h0);
    q.y = *reinterpret_cast<unsigned int*>(&h1);
    g_quadh[tiled_idx(yq, xq)] = q;
}

// ---------------------------------------------------------------------------
// grid = (23, 256): blockIdx.y = angle PAIR, blockIdx.x = detector block slot.
// Slot -> detector block via center-out permutation (long chords dispatch
// first within each row, so the tail wave holds the shortest blocks).
// block = 256 = 8 warps; each warp: 2 angles x 4 detectors x 4 t-phases.
// lane = aq*16 + tq*4 + dq. Lane samples t-index n = 4*it + tq.
// ---------------------------------------------------------------------------
__global__ void __launch_bounds__(256, 6)
project_kernel(const float* __restrict__ angles, float* __restrict__ sino) {
    const int lane = threadIdx.x & 31;
    const int warp = threadIdx.x >> 5;
    const int aq = lane >> 4;          // 0..1
    const int tq = (lane >> 2) & 3;    // 0..3
    const int dq = lane & 3;           // 0..3

    // center-out permutation of the 23 detector blocks: 11,10,12,9,13,...
    const int i = blockIdx.x;
    const int off = (i + 1) >> 1;
    const int bx = (i & 1) ? (11 - off) : (11 + off);

    const int angle = blockIdx.y * 2 + aq;
    const int d = bx * 32 + warp * 4 + dq;

    const float theta = __ldg(&angles[angle]);
    float si, c;
    sincosf(theta, &si, &c);

    const float s = (float)d - 367.5f;
    const float CTR = 255.5f + (float)PAD;        // 527.5

    // px(n) = s*c - (n - 367.5)*si + CTR, n = 4*it + tq
    const float BX = s * c + (367.5f - (float)tq) * si + CTR;
    const float BY = s * si - (367.5f - (float)tq) * c + CTR;
    const float DX = -4.0f * si;
    const float DY = 4.0f * c;

    // ---- exact chord clipping (unpadded coords), per lane ----
    const float A = s * c + 255.5f;
    const float B = s * si + 255.5f;
    float tlo = -368.0f, thi = 368.0f;
    if (fabsf(si) > 1e-6f) {
        float u1 = (A - 512.0f) / si, u2 = (A + 1.0f) / si;
        tlo = fmaxf(tlo, fminf(u1, u2));
        thi = fminf(thi, fmaxf(u1, u2));
    } else if (A <= -1.0f || A >= 512.0f) {
        thi = tlo;
    }
    if (fabsf(c) > 1e-6f) {
        float u1 = (-1.0f - B) / c, u2 = (512.0f - B) / c;
        tlo = fmaxf(tlo, fminf(u1, u2));
        thi = fminf(thi, fmaxf(u1, u2));
    } else if (B <= -1.0f || B >= 512.0f) {
        thi = tlo;
    }
    int it0 = __float2int_rd((tlo + 367.5f - (float)tq) * 0.25f);
    int it1 = __float2int_ru((thi + 367.5f - (float)tq) * 0.25f) + 1;
    it0 = min(max(it0, 0), N_SAMP / 4);
    it1 = min(max(it1, it0), N_SAMP / 4);

    const int wit0 = __reduce_min_sync(0xFFFFFFFFu, it0);
    const int wit1 = __reduce_max_sync(0xFFFFFFFFu, it1);

    float px = BX + (float)wit0 * DX;
    float py = BY + (float)wit0 * DY;
    float acc = 0.0f;

#pragma unroll 4
    for (int it = wit0; it < wit1; ++it) {
        const int xi = __float2int_rd(px);       // coords always positive
        const int yi = __float2int_rd(py);
        const float fx = px - (float)xi;
        const float fy = py - (float)yi;
        const int idx = (((yi >> 2) * TW + (xi >> 2)) << 4)
                        + ((yi & 3) << 2) + (xi & 3);
        const uint2 q = __ldg(&g_quadh[idx]);
        const __half2 h0 = *reinterpret_cast<const __half2*>(&q.x);
        const __half2 h1 = *reinterpret_cast<const __half2*>(&q.y);
        const float2 f0 = __half22float2(h0);    // (v00, v01)
        const float2 f1 = __half22float2(h1);    // (v10, v11)
        const float top = fmaf(fx, f0.y - f0.x, f0.x);
        const float bot = fmaf(fx, f1.y - f1.x, f1.x);
        acc = fmaf(fy, bot - top, acc + top);
        px += DX;
        py += DY;
    }

    // reduce over tq (lane bits [2:3])
    acc += __shfl_xor_sync(0xFFFFFFFFu, acc, 8);
    acc += __shfl_xor_sync(0xFFFFFFFFu, acc, 4);

    if (tq == 0) {
        sino[angle * N_DET + d] = acc;   // STEP = 1.0
    }
}

// ---------------------------------------------------------------------------
extern "C" void kernel_launch(void* const* d_in, const int* in_sizes, int n_in,
                              void* d_out, int out_size) {
    const float* xin    = (const float*)d_in[0];   // [1,512,512]
    const float* rin    = (const float*)d_in[1];   // [1,512,512]
    const float* angles = (const float*)d_in[2];   // [512]

    float* out = (float*)d_out;
    float* sino_out = out;                         // [1,512,736]
    float* reco_out = out + N_ANGLES * N_DET;      // [1,512,512]

    build_and_copy_kernel<<<QUAD_BLOCKS + COPY_BLOCKS, 256>>>(
        xin, rin, (float4*)reco_out);

    {
        dim3 grid(N_DET / 32, N_ANGLES / 2);       // (23, 256)
        project_kernel<<<grid, 256>>>(angles, sino_out);
    }
}